// round 3
// baseline (speedup 1.0000x reference)
#include <cuda_runtime.h>
#include <math.h>

namespace {
constexpr int BS = 16, L = 2048, DIM = 512, G = 2, VD = 256, NC = 320;
constexpr float EPS = 1e-5f;
}

// ---------------- scratch (device globals; no allocation allowed) ----------
__device__ float g_MT[G][VD][NC];     // M^T[g][u][c] : dots = x @ MT
__device__ float g_S1[G][NC];
__device__ float g_S2[G][NC];
__device__ float g_e2[NC];
__device__ float g_part[BS][G][32][2]; // per-block partial {sum,sumsq}, fixed slots (deterministic)
__device__ float g_Bc[BS][G][NC];

// ---------------- packed f32x2 helpers (Blackwell FFMA2 pipe) --------------
__device__ __forceinline__ unsigned long long pk2(float lo, float hi) {
    unsigned long long r;
    asm("mov.b64 %0, {%1, %2};" : "=l"(r) : "f"(lo), "f"(hi));
    return r;
}
__device__ __forceinline__ void upk2(unsigned long long v, float &lo, float &hi) {
    asm("mov.b64 {%0, %1}, %2;" : "=f"(lo), "=f"(hi) : "l"(v));
}
__device__ __forceinline__ unsigned long long ffma2(unsigned long long a,
                                                    unsigned long long b,
                                                    unsigned long long c) {
    unsigned long long d;
    asm("fma.rn.f32x2 %0, %1, %2, %3;" : "=l"(d) : "l"(a), "l"(b), "l"(c));
    return d;
}

// ---------------- K0: fold W, gn_weight, emb into M^T; S1/S2/e2 ------------
// M[g][c][u] = sum_o W[g][o][u] * gnw[g*VD+o] * emb[c][o]
__global__ void k0_prep(const float* __restrict__ W,
                        const float* __restrict__ gw,
                        const float* __restrict__ gb,
                        const float* __restrict__ emb) {
    const int c = blockIdx.x, g = blockIdx.y, t = threadIdx.x; // t = u (and o for reductions)
    __shared__ float sv[VD];
    const float ev = emb[c * VD + t];
    const float wv = gw[g * VD + t];
    const float bv = gb[g * VD + t];
    const float s = wv * ev;
    sv[t] = s;
    float r1 = s, r2 = bv * ev, r3 = ev * ev;
    __syncthreads();

    const float* Wg = W + g * VD * VD + t;
    float acc = 0.f;
#pragma unroll 8
    for (int o = 0; o < VD; ++o) acc = fmaf(Wg[o * VD], sv[o], acc);
    g_MT[g][t][c] = acc;

    const unsigned FULL = 0xffffffffu;
#pragma unroll
    for (int off = 16; off; off >>= 1) {
        r1 += __shfl_xor_sync(FULL, r1, off);
        r2 += __shfl_xor_sync(FULL, r2, off);
        r3 += __shfl_xor_sync(FULL, r3, off);
    }
    __shared__ float rs[3][8];
    const int w = t >> 5, lane = t & 31;
    if (lane == 0) { rs[0][w] = r1; rs[1][w] = r2; rs[2][w] = r3; }
    __syncthreads();
    if (t == 0) {
        float a1 = 0.f, a2 = 0.f, a3 = 0.f;
#pragma unroll
        for (int i = 0; i < 8; ++i) { a1 += rs[0][i]; a2 += rs[1][i]; a3 += rs[2][i]; }
        g_S1[g][c] = a1;
        g_S2[g][c] = a2;
        if (g == 0) g_e2[c] = a3;
    }
}

// ---------------- K1: ze = X_g @ W_g^T tile GEMM, accumulate sum/sumsq -----
// grid (otile=2, ltile=16, bg=32), 256 thr, 128x128 tile, packed f32x2 FMAs.
__global__ __launch_bounds__(256, 2) void k1_stats(const float* __restrict__ x,
                                                   const float* __restrict__ W) {
    const int b = blockIdx.z >> 1, g = blockIdx.z & 1;
    const int l0 = blockIdx.y * 128, o0 = blockIdx.x * 128;
    const int tid = threadIdx.x;

    __shared__ float As[8][128];
    __shared__ float Bs[8][128];

    const float* Ag = x + ((size_t)(b * L + l0)) * DIM + g * VD;   // row stride DIM
    const float* Bg = W + g * VD * VD + (size_t)o0 * VD;           // row (o) stride VD

    const int arow = tid >> 1;
    const int acol = (tid & 1) * 4;
    const int tl = (tid >> 4) * 8;   // l base in tile
    const int to = (tid & 15) * 8;   // o base in tile

    unsigned long long acc[4][8];
#pragma unroll
    for (int i = 0; i < 4; ++i)
#pragma unroll
        for (int j = 0; j < 8; ++j) acc[i][j] = 0ull;

    for (int k0 = 0; k0 < VD; k0 += 8) {
        const float4 av = *(const float4*)(Ag + (size_t)arow * DIM + k0 + acol);
        const float4 bv = *(const float4*)(Bg + (size_t)arow * VD + k0 + acol);
        __syncthreads();
        As[acol + 0][arow] = av.x; As[acol + 1][arow] = av.y;
        As[acol + 2][arow] = av.z; As[acol + 3][arow] = av.w;
        Bs[acol + 0][arow] = bv.x; Bs[acol + 1][arow] = bv.y;
        Bs[acol + 2][arow] = bv.z; Bs[acol + 3][arow] = bv.w;
        __syncthreads();
#pragma unroll
        for (int k = 0; k < 8; ++k) {
            const float4 a0 = *(const float4*)&As[k][tl];
            const float4 a1 = *(const float4*)&As[k][tl + 4];
            const float4 b0 = *(const float4*)&Bs[k][to];
            const float4 b1 = *(const float4*)&Bs[k][to + 4];
            const unsigned long long a2[4] = { pk2(a0.x, a0.y), pk2(a0.z, a0.w),
                                               pk2(a1.x, a1.y), pk2(a1.z, a1.w) };
            const float bb[8] = { b0.x, b0.y, b0.z, b0.w, b1.x, b1.y, b1.z, b1.w };
#pragma unroll
            for (int j = 0; j < 8; ++j) {
                const unsigned long long b2 = pk2(bb[j], bb[j]);
#pragma unroll
                for (int i = 0; i < 4; ++i) acc[i][j] = ffma2(a2[i], b2, acc[i][j]);
            }
        }
    }

    // local sum / sumsq over this thread's 64 outputs
    float ts = 0.f, tss = 0.f;
#pragma unroll
    for (int i = 0; i < 4; ++i)
#pragma unroll
        for (int j = 0; j < 8; ++j) {
            float lo, hi; upk2(acc[i][j], lo, hi);
            ts += lo + hi;
            tss = fmaf(lo, lo, tss); tss = fmaf(hi, hi, tss);
        }
    const unsigned FULL = 0xffffffffu;
#pragma unroll
    for (int off = 16; off; off >>= 1) {
        ts  += __shfl_xor_sync(FULL, ts, off);
        tss += __shfl_xor_sync(FULL, tss, off);
    }
    __shared__ float sred[2][8];
    const int w = tid >> 5, lane = tid & 31;
    if (lane == 0) { sred[0][w] = ts; sred[1][w] = tss; }
    __syncthreads();
    if (tid == 0) {
        float s = 0.f, ss = 0.f;
#pragma unroll
        for (int i = 0; i < 8; ++i) { s += sred[0][i]; ss += sred[1][i]; }
        const int slot = blockIdx.y * 2 + blockIdx.x;
        g_part[b][g][slot][0] = s;
        g_part[b][g][slot][1] = ss;
    }
}

// ---------------- K2: finalize mean/var -> per-code bias Bc ----------------
__global__ void k2_finalize() {
    const int b = blockIdx.x, g = blockIdx.y, c = threadIdx.x;
    __shared__ float s_mean, s_sd;
    if (c == 0) {
        float sum = 0.f, ssq = 0.f;
#pragma unroll
        for (int i = 0; i < 32; ++i) { sum += g_part[b][g][i][0]; ssq += g_part[b][g][i][1]; }
        const float invN = 1.f / (float)(VD * L);
        const float mean = sum * invN;
        const float var = ssq * invN - mean * mean;
        s_mean = mean;
        s_sd = sqrtf(var + EPS);
    }
    __syncthreads();
    g_Bc[b][g][c] = s_mean * g_S1[g][c] + (0.5f * g_e2[c] - g_S2[g][c]) * s_sd;
}

// ---------------- K3: dots = X @ M^T, argmax, gather codes -----------------
// grid (ltile=64, g=2, b=16), 256 thr. Tile: 32 tokens x 320 codes, K=256.
// warp w owns rows w*4..w*4+3; lane owns codes lane*10..lane*10+9.
__global__ __launch_bounds__(256, 2) void k3_vq(const float* __restrict__ x,
                                                const float* __restrict__ emb,
                                                float* __restrict__ out) {
    const int b = blockIdx.z, g = blockIdx.y, l0 = blockIdx.x * 32;
    const int tid = threadIdx.x, w = tid >> 5, lane = tid & 31;

    __shared__ float Ms[16][NC];
    __shared__ float As[16][32];

    float Bcl[10];
#pragma unroll
    for (int j = 0; j < 10; ++j) Bcl[j] = g_Bc[b][g][lane * 10 + j];

    unsigned long long acc[4][5];
#pragma unroll
    for (int i = 0; i < 4; ++i)
#pragma unroll
        for (int j = 0; j < 5; ++j) acc[i][j] = 0ull;

    const float* xrow = x + ((size_t)(b * L + l0)) * DIM + g * VD;
    const float* Mg = &g_MT[g][0][0];

    for (int k0 = 0; k0 < VD; k0 += 16) {
        __syncthreads();
        for (int idx = tid; idx < 1280; idx += 256) {
            const int r = idx / 80, col = (idx % 80) * 4;
            *(float4*)&Ms[r][col] = *(const float4*)(Mg + (size_t)(k0 + r) * NC + col);
        }
        if (tid < 128) {
            const int l = tid >> 2, q = tid & 3;
            const float4 v = *(const float4*)(xrow + (size_t)l * DIM + k0 + q * 4);
            As[q * 4 + 0][l] = v.x; As[q * 4 + 1][l] = v.y;
            As[q * 4 + 2][l] = v.z; As[q * 4 + 3][l] = v.w;
        }
        __syncthreads();
#pragma unroll
        for (int k = 0; k < 16; ++k) {
            const float4 af = *(const float4*)&As[k][w * 4];
            const unsigned long long a2[4] = { pk2(af.x, af.x), pk2(af.y, af.y),
                                               pk2(af.z, af.z), pk2(af.w, af.w) };
            const unsigned long long* bp = (const unsigned long long*)&Ms[k][lane * 10];
#pragma unroll
            for (int j = 0; j < 5; ++j) {
                const unsigned long long b2 = bp[j];
#pragma unroll
                for (int i = 0; i < 4; ++i) acc[i][j] = ffma2(a2[i], b2, acc[i][j]);
            }
        }
    }

    const unsigned FULL = 0xffffffffu;
    int bestc[4];
#pragma unroll
    for (int i = 0; i < 4; ++i) {
        float bv = -1e30f; int bc = 0;
#pragma unroll
        for (int j = 0; j < 5; ++j) {
            float lo, hi; upk2(acc[i][j], lo, hi);
            const int o0 = lane * 10 + 2 * j;
            const float s0 = lo - Bcl[2 * j];
            const float s1 = hi - Bcl[2 * j + 1];
            if (s0 > bv || (s0 == bv && o0 < bc)) { bv = s0; bc = o0; }
            if (s1 > bv || (s1 == bv && (o0 + 1) < bc)) { bv = s1; bc = o0 + 1; }
        }
#pragma unroll
        for (int off = 16; off; off >>= 1) {
            const float ov = __shfl_xor_sync(FULL, bv, off);
            const int oc = __shfl_xor_sync(FULL, bc, off);
            if (ov > bv || (ov == bv && oc < bc)) { bv = ov; bc = oc; }
        }
        bestc[i] = bc;
    }

    // gather: out[b, l, g*VD : (g+1)*VD] = emb[bestc]
    float* orow = out + ((size_t)(b * L + l0 + w * 4)) * DIM + g * VD;
#pragma unroll
    for (int i = 0; i < 4; ++i) {
        const float4* src = (const float4*)(emb + (size_t)bestc[i] * VD);
        float4* dst = (float4*)(orow + (size_t)i * DIM);
        dst[lane] = src[lane];
        dst[lane + 32] = src[lane + 32];
    }
}

// ---------------- launch ---------------------------------------------------
extern "C" void kernel_launch(void* const* d_in, const int* in_sizes, int n_in,
                              void* d_out, int out_size) {
    (void)in_sizes; (void)n_in; (void)out_size;
    const float* x   = (const float*)d_in[0];
    const float* W   = (const float*)d_in[1];
    const float* gw  = (const float*)d_in[2];
    const float* gb  = (const float*)d_in[3];
    const float* emb = (const float*)d_in[4];
    float* out = (float*)d_out;

    k0_prep<<<dim3(NC, G), VD>>>(W, gw, gb, emb);
    k1_stats<<<dim3(2, 16, 32), 256>>>(x, W);
    k2_finalize<<<dim3(BS, G), NC>>>();
    k3_vq<<<dim3(L / 32, G, BS), 256>>>(x, emb, out);
}

// round 4
// speedup vs baseline: 1.4045x; 1.4045x over previous
#include <cuda_runtime.h>
#include <math.h>

namespace {
constexpr int BS = 16, L = 2048, DIM = 512, G = 2, VD = 256, NC = 320;
constexpr float EPS = 1e-5f;
}

// ---------------- scratch (device globals; no allocation allowed) ----------
__device__ float g_MT[G][VD][NC];      // M^T[g][u][c] : dots = x @ MT
__device__ float g_S1[G][NC];
__device__ float g_S2[G][NC];
__device__ float g_e2[NC];
__device__ float g_part[BS][G][32][2]; // per-block partial {sum,sumsq}
__device__ float g_Bc[BS][G][NC];

// ---------------- packed f32x2 helpers (Blackwell FFMA2 pipe) --------------
__device__ __forceinline__ unsigned long long pk2(float lo, float hi) {
    unsigned long long r;
    asm("mov.b64 %0, {%1, %2};" : "=l"(r) : "f"(lo), "f"(hi));
    return r;
}
__device__ __forceinline__ void upk2(unsigned long long v, float &lo, float &hi) {
    asm("mov.b64 {%0, %1}, %2;" : "=f"(lo), "=f"(hi) : "l"(v));
}
__device__ __forceinline__ unsigned long long ffma2(unsigned long long a,
                                                    unsigned long long b,
                                                    unsigned long long c) {
    unsigned long long d;
    asm("fma.rn.f32x2 %0, %1, %2, %3;" : "=l"(d) : "l"(a), "l"(b), "l"(c));
    return d;
}

// ---------------- cp.async helpers -----------------------------------------
__device__ __forceinline__ unsigned smem_u32(const void* p) {
    return (unsigned)__cvta_generic_to_shared(p);
}
__device__ __forceinline__ void cp_async16(unsigned dst, const void* src) {
    asm volatile("cp.async.cg.shared.global [%0], [%1], 16;\n" :: "r"(dst), "l"(src));
}
__device__ __forceinline__ void cp_commit() {
    asm volatile("cp.async.commit_group;\n");
}
__device__ __forceinline__ void cp_wait0() {
    asm volatile("cp.async.wait_group 0;\n" ::: "memory");
}

// ---------------- K0: fold W, gn_weight, emb into M^T; S1/S2/e2 ------------
// M[g][c][u] = sum_o W[g][o][u] * gnw[g*VD+o] * emb[c][o].  8 codes / block.
__global__ void k0_prep(const float* __restrict__ W,
                        const float* __restrict__ gw,
                        const float* __restrict__ gb,
                        const float* __restrict__ emb) {
    const int c0 = blockIdx.x * 8, g = blockIdx.y, tid = threadIdx.x;
    __shared__ float es[8][VD];   // gw-scaled emb rows

    for (int idx = tid; idx < 8 * VD; idx += 256) {
        const int c = idx >> 8, o = idx & 255;
        es[c][o] = emb[(size_t)(c0 + c) * VD + o] * gw[g * VD + o];
    }
    __syncthreads();

    // reductions: warp w owns code c0+w
    const int w = tid >> 5, lane = tid & 31;
    {
        float s1 = 0.f, s2 = 0.f, s3 = 0.f;
        const float* ec = emb + (size_t)(c0 + w) * VD;
        for (int o = lane; o < VD; o += 32) {
            const float e = ec[o];
            s1 = fmaf(e, gw[g * VD + o], s1);
            s2 = fmaf(e, gb[g * VD + o], s2);
            s3 = fmaf(e, e, s3);
        }
        const unsigned FULL = 0xffffffffu;
#pragma unroll
        for (int off = 16; off; off >>= 1) {
            s1 += __shfl_xor_sync(FULL, s1, off);
            s2 += __shfl_xor_sync(FULL, s2, off);
            s3 += __shfl_xor_sync(FULL, s3, off);
        }
        if (lane == 0) {
            g_S1[g][c0 + w] = s1;
            g_S2[g][c0 + w] = s2;
            if (g == 0) g_e2[c0 + w] = s3;
        }
    }

    // main: thread = u, 8 codes per thread; W row reads coalesced
    float acc[8];
#pragma unroll
    for (int c = 0; c < 8; ++c) acc[c] = 0.f;
    const float* Wg = W + (size_t)g * VD * VD + tid;
#pragma unroll 4
    for (int o = 0; o < VD; ++o) {
        const float wv = Wg[(size_t)o * VD];
#pragma unroll
        for (int c = 0; c < 8; ++c) acc[c] = fmaf(wv, es[c][o], acc[c]);
    }
    float4* dst = (float4*)&g_MT[g][tid][c0];
    dst[0] = make_float4(acc[0], acc[1], acc[2], acc[3]);
    dst[1] = make_float4(acc[4], acc[5], acc[6], acc[7]);
}

// ---------------- K1: ze = X_g @ W_g^T, accumulate sum/sumsq ---------------
// 128x128 tile, K-chunks of 8, 2-stage double buffer, token-pairs packed.
__global__ __launch_bounds__(256, 2) void k1_stats(const float* __restrict__ x,
                                                   const float* __restrict__ W) {
    const int b = blockIdx.z >> 1, g = blockIdx.z & 1;
    const int l0 = blockIdx.y * 128, o0 = blockIdx.x * 128;
    const int tid = threadIdx.x;

    __shared__ __align__(16) float As[2][8][128];  // [k][l]
    __shared__ __align__(16) float Bs[2][8][128];  // [k][o]

    const float* Ag = x + ((size_t)(b * L + l0)) * DIM + g * VD;
    const float* Bg = W + (size_t)g * VD * VD + (size_t)o0 * VD;

    const int arow = tid >> 1;          // l (and o) row this thread loads
    const int acol = (tid & 1) * 4;     // k offset
    const int tl = (tid >> 4) * 8;      // 8 tokens owned (pairs)
    const int om = tid & 15;            // o = om + 16*j (interleaved, conflict-free)

    unsigned long long acc[4][8];
#pragma unroll
    for (int i = 0; i < 4; ++i)
#pragma unroll
        for (int j = 0; j < 8; ++j) acc[i][j] = 0ull;

    // prologue: chunk 0
    {
        const float4 av = *(const float4*)(Ag + (size_t)arow * DIM + acol);
        const float4 bv = *(const float4*)(Bg + (size_t)arow * VD + acol);
        As[0][acol + 0][arow] = av.x; As[0][acol + 1][arow] = av.y;
        As[0][acol + 2][arow] = av.z; As[0][acol + 3][arow] = av.w;
        Bs[0][acol + 0][arow] = bv.x; Bs[0][acol + 1][arow] = bv.y;
        Bs[0][acol + 2][arow] = bv.z; Bs[0][acol + 3][arow] = bv.w;
    }
    __syncthreads();

    int s = 0;
    for (int kc = 0; kc < 32; ++kc) {
        float4 an, bn;
        if (kc < 31) {
            const int kb = (kc + 1) * 8;
            an = *(const float4*)(Ag + (size_t)arow * DIM + kb + acol);
            bn = *(const float4*)(Bg + (size_t)arow * VD + kb + acol);
        }
#pragma unroll
        for (int k = 0; k < 8; ++k) {
            unsigned long long ap[4];
#pragma unroll
            for (int i = 0; i < 4; ++i)
                ap[i] = *(const unsigned long long*)&As[s][k][tl + 2 * i];
#pragma unroll
            for (int j = 0; j < 8; ++j) {
                const float bvv = Bs[s][k][om + 16 * j];
                const unsigned long long bd = pk2(bvv, bvv);
#pragma unroll
                for (int i = 0; i < 4; ++i) acc[i][j] = ffma2(ap[i], bd, acc[i][j]);
            }
        }
        if (kc < 31) {
            const int t = s ^ 1;
            As[t][acol + 0][arow] = an.x; As[t][acol + 1][arow] = an.y;
            As[t][acol + 2][arow] = an.z; As[t][acol + 3][arow] = an.w;
            Bs[t][acol + 0][arow] = bn.x; Bs[t][acol + 1][arow] = bn.y;
            Bs[t][acol + 2][arow] = bn.z; Bs[t][acol + 3][arow] = bn.w;
        }
        __syncthreads();
        s ^= 1;
    }

    // local sum / sumsq over this thread's 64 outputs
    float ts = 0.f, tss = 0.f;
#pragma unroll
    for (int i = 0; i < 4; ++i)
#pragma unroll
        for (int j = 0; j < 8; ++j) {
            float lo, hi; upk2(acc[i][j], lo, hi);
            ts += lo + hi;
            tss = fmaf(lo, lo, tss); tss = fmaf(hi, hi, tss);
        }
    const unsigned FULL = 0xffffffffu;
#pragma unroll
    for (int off = 16; off; off >>= 1) {
        ts  += __shfl_xor_sync(FULL, ts, off);
        tss += __shfl_xor_sync(FULL, tss, off);
    }
    __shared__ float sred[2][8];
    const int w = tid >> 5, lane = tid & 31;
    if (lane == 0) { sred[0][w] = ts; sred[1][w] = tss; }
    __syncthreads();
    if (tid == 0) {
        float su = 0.f, ss = 0.f;
#pragma unroll
        for (int i = 0; i < 8; ++i) { su += sred[0][i]; ss += sred[1][i]; }
        const int slot = blockIdx.y * 2 + blockIdx.x;
        g_part[b][g][slot][0] = su;
        g_part[b][g][slot][1] = ss;
    }
}

// ---------------- K2: finalize mean/var -> per-code bias Bc ----------------
__global__ void k2_finalize() {
    const int b = blockIdx.x, g = blockIdx.y, c = threadIdx.x;
    __shared__ float s_mean, s_sd;
    if (c == 0) {
        float sum = 0.f, ssq = 0.f;
#pragma unroll
        for (int i = 0; i < 32; ++i) { sum += g_part[b][g][i][0]; ssq += g_part[b][g][i][1]; }
        const float invN = 1.f / (float)(VD * L);
        const float mean = sum * invN;
        const float var = ssq * invN - mean * mean;
        s_mean = mean;
        s_sd = sqrtf(var + EPS);
    }
    __syncthreads();
    g_Bc[b][g][c] = s_mean * g_S1[g][c] + (0.5f * g_e2[c] - g_S2[g][c]) * s_sd;
}

// ---------------- K3: dots = X @ M^T, argmax, gather codes -----------------
// 64 tokens x 320 codes / block, K chunks of 16, cp.async double-buffered Ms.
// warp w owns tokens w*8..w*8+7; lane owns code pairs c = j*64 + lane*2.
__global__ __launch_bounds__(256, 2) void k3_vq(const float* __restrict__ x,
                                                const float* __restrict__ emb,
                                                float* __restrict__ out) {
    const int b = blockIdx.z, g = blockIdx.y, l0 = blockIdx.x * 64;
    const int tid = threadIdx.x, w = tid >> 5, lane = tid & 31;

    __shared__ __align__(16) float Ms[2][16][NC];   // 2 x 20 KB
    __shared__ float As[2][16][66];                 // row 66: conflict-free STS

    const float* xrow = x + ((size_t)(b * L + l0)) * DIM + g * VD;
    const float* Mg = &g_MT[g][0][0];

    const int la = tid >> 2;            // token this thread loads (0..63)
    const int qa = tid & 3;             // k-quad

    unsigned long long acc[8][5];
#pragma unroll
    for (int i = 0; i < 8; ++i)
#pragma unroll
        for (int j = 0; j < 5; ++j) acc[i][j] = 0ull;

    // prologue: chunk 0
#pragma unroll
    for (int n = 0; n < 5; ++n) {
        const int idx = tid + n * 256;
        const int r = idx / 80, col = (idx % 80) * 4;
        cp_async16(smem_u32(&Ms[0][r][col]), Mg + (size_t)r * NC + col);
    }
    cp_commit();
    {
        const float4 v = *(const float4*)(xrow + (size_t)la * DIM + qa * 4);
        As[0][qa * 4 + 0][la] = v.x; As[0][qa * 4 + 1][la] = v.y;
        As[0][qa * 4 + 2][la] = v.z; As[0][qa * 4 + 3][la] = v.w;
    }
    cp_wait0();
    __syncthreads();

    int s = 0;
    for (int step = 0; step < 16; ++step) {
        float4 an;
        if (step < 15) {
            const int kb = (step + 1) * 16;
#pragma unroll
            for (int n = 0; n < 5; ++n) {
                const int idx = tid + n * 256;
                const int r = idx / 80, col = (idx % 80) * 4;
                cp_async16(smem_u32(&Ms[s ^ 1][r][col]),
                           Mg + (size_t)(kb + r) * NC + col);
            }
            cp_commit();
            an = *(const float4*)(xrow + (size_t)la * DIM + kb + qa * 4);
        }
#pragma unroll
        for (int k = 0; k < 16; ++k) {
            unsigned long long m[5];
#pragma unroll
            for (int j = 0; j < 5; ++j)
                m[j] = *(const unsigned long long*)&Ms[s][k][j * 64 + lane * 2];
#pragma unroll
            for (int i = 0; i < 8; ++i) {
                const float av = As[s][k][w * 8 + i];
                const unsigned long long ad = pk2(av, av);
#pragma unroll
                for (int j = 0; j < 5; ++j) acc[i][j] = ffma2(ad, m[j], acc[i][j]);
            }
        }
        if (step < 15) {
            const int t = s ^ 1;
            As[t][qa * 4 + 0][la] = an.x; As[t][qa * 4 + 1][la] = an.y;
            As[t][qa * 4 + 2][la] = an.z; As[t][qa * 4 + 3][la] = an.w;
        }
        cp_wait0();
        __syncthreads();
        s ^= 1;
    }

    // bias + argmax (tie-break: lowest code index, matching argmin-first)
    float2 bc[5];
#pragma unroll
    for (int j = 0; j < 5; ++j)
        bc[j] = *(const float2*)&g_Bc[b][g][j * 64 + lane * 2];

    const unsigned FULL = 0xffffffffu;
    int bestc[8];
#pragma unroll
    for (int i = 0; i < 8; ++i) {
        float bv = -1e30f; int bi = 0x7fffffff;
#pragma unroll
        for (int j = 0; j < 5; ++j) {
            float lo, hi; upk2(acc[i][j], lo, hi);
            const int c0 = j * 64 + lane * 2;
            const float s0 = lo - bc[j].x;
            const float s1 = hi - bc[j].y;
            if (s0 > bv || (s0 == bv && c0 < bi)) { bv = s0; bi = c0; }
            if (s1 > bv || (s1 == bv && (c0 + 1) < bi)) { bv = s1; bi = c0 + 1; }
        }
#pragma unroll
        for (int off = 16; off; off >>= 1) {
            const float ov = __shfl_xor_sync(FULL, bv, off);
            const int oc = __shfl_xor_sync(FULL, bi, off);
            if (ov > bv || (ov == bv && oc < bi)) { bv = ov; bi = oc; }
        }
        bestc[i] = bi;
    }

    // gather: out[b, l, g*VD : (g+1)*VD] = emb[bestc]
    float* orow = out + ((size_t)(b * L + l0 + w * 8)) * DIM + g * VD;
#pragma unroll
    for (int i = 0; i < 8; ++i) {
        const float4* src = (const float4*)(emb + (size_t)bestc[i] * VD);
        float4* dst = (float4*)(orow + (size_t)i * DIM);
        dst[lane] = src[lane];
        dst[lane + 32] = src[lane + 32];
    }
}

// ---------------- launch ---------------------------------------------------
extern "C" void kernel_launch(void* const* d_in, const int* in_sizes, int n_in,
                              void* d_out, int out_size) {
    (void)in_sizes; (void)n_in; (void)out_size;
    const float* x   = (const float*)d_in[0];
    const float* W   = (const float*)d_in[1];
    const float* gw  = (const float*)d_in[2];
    const float* gb  = (const float*)d_in[3];
    const float* emb = (const float*)d_in[4];
    float* out = (float*)d_out;

    k0_prep<<<dim3(NC / 8, G), 256>>>(W, gw, gb, emb);
    k1_stats<<<dim3(2, 16, 32), 256>>>(x, W);
    k2_finalize<<<dim3(BS, G), NC>>>();
    k3_vq<<<dim3(L / 64, G, BS), 256>>>(x, emb, out);
}